// round 2
// baseline (speedup 1.0000x reference)
#include <cuda_runtime.h>
#include <math.h>

#define BB 8
#define CC 128
#define NN 512
#define TT 64
#define KTOP 409   // int(0.8*512)

// ---------------- scratch (device globals; no allocation) ----------------
__device__ float g_xw[(size_t)BB*CC*NN*TT];   // xw = W_w x + b     [B,C,N,T]
__device__ float g_xh[(size_t)BB*CC*NN*TT];   // diffusion output   [B,C,N,T]
__device__ float g_h [(size_t)BB*NN*CC];      // h[b,n,c]
__device__ float g_wh1[BB*NN];
__device__ float g_wh2[BB*NN];
__device__ float g_s [(size_t)2*BB*NN*NN];    // relu(scale*S1), relu(scale*S2)
__device__ float g_adj[(size_t)BB*NN*NN];     // masked adjacency  [b,n,m]
__device__ float g_M [CC*CC];                 // M = conv_w @ theta^T

// ---------------- K0: M[d][e] = sum_c conv_w[d,c]*theta[e,c] ----------------
__global__ void k0_kernel(const float* __restrict__ conv_w,
                          const float* __restrict__ theta)
{
    int d = blockIdx.x;        // 0..127
    int e = threadIdx.x;       // 0..127
    float s = 0.f;
    #pragma unroll 8
    for (int c = 0; c < CC; c++)
        s += __ldg(conv_w + d*CC + c) * __ldg(theta + e*CC + c);
    g_M[d*CC + e] = s;
}

// ---------------- K1: xw = W x + b ; h = sum_t xw ; Wh1/Wh2 ----------------
__global__ void __launch_bounds__(256) k1_kernel(
    const float* __restrict__ x, const float* __restrict__ Ww,
    const float* __restrict__ Wb, const float* __restrict__ av)
{
    extern __shared__ float sm[];
    float* Ws = sm;              // [128][130] padded
    float* Xs = sm + CC*130;     // [128][64]
    __shared__ float hpart[CC*8];
    __shared__ float rb1[8], rb2[8];

    const int tid = threadIdx.x;
    const int b = blockIdx.x >> 9;
    const int n = blockIdx.x & (NN-1);

    // load W (row-major, padded stride 130)
    for (int q = tid; q < CC*CC/4; q += 256) {
        int d  = q >> 5;
        int c0 = (q & 31) << 2;
        float4 w4 = *(const float4*)(Ww + d*CC + c0);
        float* dst = Ws + d*130 + c0;
        dst[0]=w4.x; dst[1]=w4.y; dst[2]=w4.z; dst[3]=w4.w;
    }
    // load X tile x[b,:,n,:]
    const float* xb = x + ((size_t)b*CC*NN + n) * TT;
    for (int q = tid; q < CC*TT/4; q += 256) {
        int c  = q >> 4;
        int t4 = (q & 15) << 2;
        *(float4*)(Xs + c*TT + t4) = *(const float4*)(xb + (size_t)c*NN*TT + t4);
    }
    __syncthreads();

    const int dg = tid >> 3, tg = tid & 7;
    const int d0 = dg*4, t0 = tg*8;
    float acc[4][8];
    #pragma unroll
    for (int i=0;i<4;i++)
        #pragma unroll
        for (int j=0;j<8;j++) acc[i][j]=0.f;

    #pragma unroll 2
    for (int c=0;c<CC;c++){
        float wv[4];
        #pragma unroll
        for (int i=0;i<4;i++) wv[i] = Ws[(d0+i)*130 + c];
        float4 xa = *(float4*)(Xs + c*TT + t0);
        float4 xc = *(float4*)(Xs + c*TT + t0 + 4);
        float xv[8] = {xa.x,xa.y,xa.z,xa.w,xc.x,xc.y,xc.z,xc.w};
        #pragma unroll
        for (int i=0;i<4;i++)
            #pragma unroll
            for (int j=0;j<8;j++) acc[i][j] += wv[i]*xv[j];
    }

    float* outp = g_xw + ((size_t)b*CC*NN + n) * TT;
    #pragma unroll
    for (int i=0;i<4;i++){
        float bias = Wb[d0+i];
        float rs = 0.f;
        #pragma unroll
        for (int j=0;j<8;j++){ acc[i][j] += bias; rs += acc[i][j]; }
        *(float4*)(outp + (size_t)(d0+i)*NN*TT + t0)
            = make_float4(acc[i][0],acc[i][1],acc[i][2],acc[i][3]);
        *(float4*)(outp + (size_t)(d0+i)*NN*TT + t0+4)
            = make_float4(acc[i][4],acc[i][5],acc[i][6],acc[i][7]);
        hpart[(d0+i)*8 + tg] = rs;
    }
    __syncthreads();

    float p1 = 0.f, p2 = 0.f;
    if (tid < CC){
        float hv = 0.f;
        #pragma unroll
        for (int j=0;j<8;j++) hv += hpart[tid*8+j];
        g_h[((size_t)b*NN+n)*CC + tid] = hv;
        p1 = hv*av[tid];
        p2 = hv*av[CC+tid];
    }
    #pragma unroll
    for (int o=16;o;o>>=1){
        p1 += __shfl_xor_sync(0xffffffffu,p1,o);
        p2 += __shfl_xor_sync(0xffffffffu,p2,o);
    }
    if ((tid&31)==0){ rb1[tid>>5]=p1; rb2[tid>>5]=p2; }
    __syncthreads();
    if (tid==0){
        float s1=0.f, s2=0.f;
        #pragma unroll
        for (int i=0;i<8;i++){ s1+=rb1[i]; s2+=rb2[i]; }
        g_wh1[b*NN+n]=s1; g_wh2[b*NN+n]=s2;
    }
}

// ---------------- K2a: S = relu(scale * A B^T)  (A=h[b], B=memory or h[b]) --
__global__ void __launch_bounds__(256) k2a_kernel(const float* __restrict__ mem)
{
    __shared__ float As[64][17];
    __shared__ float Bs[64][17];
    const int z = blockIdx.z, b = z>>1, which = z&1;
    const int n0 = blockIdx.x*64, m0 = blockIdx.y*64;
    const float* A  = g_h + (size_t)b*NN*CC;
    const float* Bp = which ? A : mem;
    float* out = g_s + (size_t)which*BB*NN*NN + (size_t)b*NN*NN;
    const int tid = threadIdx.x;
    const int nl0 = (tid>>4)*4, ml0 = (tid&15)*4;
    const int rr = tid>>2, kq = (tid&3)*4;

    float acc[4][4];
    #pragma unroll
    for (int i=0;i<4;i++)
        #pragma unroll
        for (int j=0;j<4;j++) acc[i][j]=0.f;

    for (int k0=0;k0<CC;k0+=16){
        float4 a4 = *(const float4*)(A  + (size_t)(n0+rr)*CC + k0 + kq);
        As[rr][kq  ]=a4.x; As[rr][kq+1]=a4.y; As[rr][kq+2]=a4.z; As[rr][kq+3]=a4.w;
        float4 b4 = *(const float4*)(Bp + (size_t)(m0+rr)*CC + k0 + kq);
        Bs[rr][kq  ]=b4.x; Bs[rr][kq+1]=b4.y; Bs[rr][kq+2]=b4.z; Bs[rr][kq+3]=b4.w;
        __syncthreads();
        #pragma unroll
        for (int k=0;k<16;k++){
            float ar[4], br[4];
            #pragma unroll
            for (int i=0;i<4;i++) ar[i]=As[nl0+i][k];
            #pragma unroll
            for (int j=0;j<4;j++) br[j]=Bs[ml0+j][k];
            #pragma unroll
            for (int i=0;i<4;i++)
                #pragma unroll
                for (int j=0;j<4;j++) acc[i][j] += ar[i]*br[j];
        }
        __syncthreads();
    }
    const float scale = 0.08838834764831845f;  // 1/sqrt(128)
    #pragma unroll
    for (int i=0;i<4;i++){
        float4 v;
        v.x = fmaxf(acc[i][0]*scale, 0.f);
        v.y = fmaxf(acc[i][1]*scale, 0.f);
        v.z = fmaxf(acc[i][2]*scale, 0.f);
        v.w = fmaxf(acc[i][3]*scale, 0.f);
        *(float4*)(out + (size_t)(n0+nl0+i)*NN + m0 + ml0) = v;
    }
}

// ---------------- K2b: softmaxes + combine + softmax + top-k mask ----------
__device__ __forceinline__ float blkMax(float v, float* buf){
    #pragma unroll
    for (int o=16;o;o>>=1) v = fmaxf(v, __shfl_xor_sync(0xffffffffu,v,o));
    if ((threadIdx.x&31)==0) buf[threadIdx.x>>5]=v;
    __syncthreads();
    float r = buf[0];
    #pragma unroll
    for (int i=1;i<8;i++) r = fmaxf(r, buf[i]);
    __syncthreads();
    return r;
}
__device__ __forceinline__ float blkSum(float v, float* buf){
    #pragma unroll
    for (int o=16;o;o>>=1) v += __shfl_xor_sync(0xffffffffu,v,o);
    if ((threadIdx.x&31)==0) buf[threadIdx.x>>5]=v;
    __syncthreads();
    float r = 0.f;
    #pragma unroll
    for (int i=0;i<8;i++) r += buf[i];
    __syncthreads();
    return r;
}

__global__ void __launch_bounds__(256) k2b_kernel(
    const float* __restrict__ cw,  const float* __restrict__ cwa,
    const float* __restrict__ fcw, const float* __restrict__ fcb)
{
    __shared__ float awrow[NN];
    __shared__ float sb[NN];
    __shared__ float rbuf[8];
    __shared__ int   ibuf[8];
    const int tid = threadIdx.x;
    const int b = blockIdx.x >> 9, n = blockIdx.x & (NN-1);
    const size_t rowoff = ((size_t)b*NN + n)*NN;
    const float* s1r = g_s + rowoff;
    const float* s2r = g_s + (size_t)BB*NN*NN + rowoff;

    float v1[2], v2[2];
    v1[0]=s1r[tid]; v1[1]=s1r[tid+256];
    v2[0]=s2r[tid]; v2[1]=s2r[tid+256];

    float m1 = blkMax(fmaxf(v1[0],v1[1]), rbuf);
    float e1a=expf(v1[0]-m1), e1b=expf(v1[1]-m1);
    float z1 = blkSum(e1a+e1b, rbuf);
    float a1[2] = {e1a/z1, e1b/z1};

    float m2 = blkMax(fmaxf(v2[0],v2[1]), rbuf);
    float e2a=expf(v2[0]-m2), e2b=expf(v2[1]-m2);
    float z2 = blkSum(e2a+e2b, rbuf);
    float a2[2] = {e2a/z2, e2b/z2};

    float wh1n = g_wh1[b*NN+n];
    float f0 = fcw[0], f1 = fcw[1], fb = fcb[0];
    float l[2];
    #pragma unroll
    for (int r=0;r<2;r++){
        int m_ = tid + r*256;
        float af = f0*a1[r] + f1*a2[r] + fb;
        l[r] = (wh1n + g_wh2[b*NN+m_]) * cw[(size_t)n*NN+m_]
             + af * cwa[(size_t)n*NN+m_];
    }
    float lm = blkMax(fmaxf(l[0],l[1]), rbuf);
    float ea = expf(l[0]-lm), eb = expf(l[1]-lm);
    float z  = blkSum(ea+eb, rbuf);
    float aw[2] = {ea/z, eb/z};

    awrow[tid]=aw[0]; awrow[tid+256]=aw[1];
    sb[tid]=aw[0];    sb[tid+256]=aw[1];
    __syncthreads();

    // bitonic sort ascending, 512 elems / 256 threads
    for (int ks=2; ks<=NN; ks<<=1){
        for (int j=ks>>1; j>0; j>>=1){
            #pragma unroll
            for (int rep=0; rep<2; rep++){
                int idx = tid + rep*256;
                int ixj = idx ^ j;
                if (ixj > idx){
                    float x0 = sb[idx], x1 = sb[ixj];
                    bool up = ((idx & ks) == 0);
                    bool sw = up ? (x0 > x1) : (x0 < x1);
                    if (sw){ sb[idx]=x1; sb[ixj]=x0; }
                }
            }
            __syncthreads();
        }
    }
    float thr = sb[NN - KTOP];   // 409th largest

    int cgt = (aw[0] > thr) + (aw[1] > thr);
    #pragma unroll
    for (int o=16;o;o>>=1) cgt += __shfl_xor_sync(0xffffffffu,cgt,o);
    if ((tid&31)==0) ibuf[tid>>5]=cgt;
    __syncthreads();
    if (tid==0){
        int tot=0;
        #pragma unroll
        for (int i=0;i<8;i++) tot += ibuf[i];
        int need = KTOP - tot;  // how many == thr to keep (lowest index first)
        for (int m_=0; m_<NN; m_++){
            float v = awrow[m_];
            if (v == thr){ if (need>0) need--; else awrow[m_] = 0.f; }
        }
    }
    __syncthreads();

    float* outr = g_adj + rowoff;
    #pragma unroll
    for (int r=0;r<2;r++){
        int m_ = tid + r*256;
        float v = awrow[m_];
        outr[m_] = (v >= thr) ? v : 0.f;
    }
}

// ---------------- K3: xh[b,c,m,t] = sum_n adj[b,n,m] * xw[b,c,n,t] ---------
__global__ void __launch_bounds__(256) k3_kernel()
{
    __shared__ float As[16][64];
    __shared__ float Bs[16][64];
    const int mt = blockIdx.x, c = blockIdx.y, b = blockIdx.z;
    const int m0 = mt*64;
    const int tid = threadIdx.x;
    const int ml0 = (tid & 15)*4, tl0 = (tid >> 4)*4;
    const int lk = tid >> 4, lq = (tid & 15)*4;

    float acc[4][4];
    #pragma unroll
    for (int i=0;i<4;i++)
        #pragma unroll
        for (int j=0;j<4;j++) acc[i][j]=0.f;

    const float* adjb = g_adj + (size_t)b*NN*NN;
    const float* xwb  = g_xw + ((size_t)b*CC + c)*NN*TT;

    for (int n0=0; n0<NN; n0+=16){
        *(float4*)&As[lk][lq] = *(const float4*)(adjb + (size_t)(n0+lk)*NN + m0 + lq);
        *(float4*)&Bs[lk][lq] = *(const float4*)(xwb  + (size_t)(n0+lk)*TT + lq);
        __syncthreads();
        #pragma unroll
        for (int k=0;k<16;k++){
            float4 a4 = *(float4*)&As[k][ml0];
            float4 b4 = *(float4*)&Bs[k][tl0];
            float ar[4] = {a4.x,a4.y,a4.z,a4.w};
            float br[4] = {b4.x,b4.y,b4.z,b4.w};
            #pragma unroll
            for (int i=0;i<4;i++)
                #pragma unroll
                for (int j=0;j<4;j++) acc[i][j] += ar[i]*br[j];
        }
        __syncthreads();
    }
    float* outp = g_xh + ((size_t)b*CC + c)*NN*TT;
    #pragma unroll
    for (int i=0;i<4;i++)
        *(float4*)(outp + (size_t)(m0+ml0+i)*TT + tl0)
            = make_float4(acc[i][0],acc[i][1],acc[i][2],acc[i][3]);
}

// ---------------- K4: out = (M xh + conv_b) * emb + x ----------------------
__global__ void __launch_bounds__(256) k4_kernel(
    const float* __restrict__ x, const float* __restrict__ cb,
    const float* __restrict__ emb, float* __restrict__ outg)
{
    extern __shared__ float sm[];
    float* Ms = sm;              // [128][130]
    float* Xs = sm + CC*130;     // [128][64]
    const int tid = threadIdx.x;
    const int b = blockIdx.x >> 9;
    const int n = blockIdx.x & (NN-1);

    for (int q = tid; q < CC*CC/4; q += 256) {
        int d  = q >> 5;
        int c0 = (q & 31) << 2;
        float4 w4 = *(const float4*)(g_M + d*CC + c0);
        float* dst = Ms + d*130 + c0;
        dst[0]=w4.x; dst[1]=w4.y; dst[2]=w4.z; dst[3]=w4.w;
    }
    const float* xhb = g_xh + ((size_t)b*CC*NN + n) * TT;
    for (int q = tid; q < CC*TT/4; q += 256) {
        int c  = q >> 4;
        int t4 = (q & 15) << 2;
        *(float4*)(Xs + c*TT + t4) = *(const float4*)(xhb + (size_t)c*NN*TT + t4);
    }
    __syncthreads();

    const int dg = tid >> 3, tg = tid & 7;
    const int d0 = dg*4, t0 = tg*8;
    float acc[4][8];
    #pragma unroll
    for (int i=0;i<4;i++)
        #pragma unroll
        for (int j=0;j<8;j++) acc[i][j]=0.f;

    #pragma unroll 2
    for (int c=0;c<CC;c++){
        float wv[4];
        #pragma unroll
        for (int i=0;i<4;i++) wv[i] = Ms[(d0+i)*130 + c];
        float4 xa = *(float4*)(Xs + c*TT + t0);
        float4 xc = *(float4*)(Xs + c*TT + t0 + 4);
        float xv[8] = {xa.x,xa.y,xa.z,xa.w,xc.x,xc.y,xc.z,xc.w};
        #pragma unroll
        for (int i=0;i<4;i++)
            #pragma unroll
            for (int j=0;j<8;j++) acc[i][j] += wv[i]*xv[j];
    }

    const float* xb = x    + ((size_t)b*CC*NN + n) * TT;
    float*       op = outg + ((size_t)b*CC*NN + n) * TT;
    #pragma unroll
    for (int i=0;i<4;i++){
        int d = d0 + i;
        float bias = cb[d];
        float ev = emb[d*NN + n];
        float4 s0 = *(const float4*)(xb + (size_t)d*NN*TT + t0);
        float4 s1 = *(const float4*)(xb + (size_t)d*NN*TT + t0 + 4);
        float sk[8] = {s0.x,s0.y,s0.z,s0.w,s1.x,s1.y,s1.z,s1.w};
        float r[8];
        #pragma unroll
        for (int j=0;j<8;j++) r[j] = (acc[i][j] + bias)*ev + sk[j];
        *(float4*)(op + (size_t)d*NN*TT + t0)     = make_float4(r[0],r[1],r[2],r[3]);
        *(float4*)(op + (size_t)d*NN*TT + t0 + 4) = make_float4(r[4],r[5],r[6],r[7]);
    }
}

// ---------------- launch -----------------------------------------------------
extern "C" void kernel_launch(void* const* d_in, const int* in_sizes, int n_in,
                              void* d_out, int out_size)
{
    const float* x      = (const float*)d_in[0];
    const float* Ww     = (const float*)d_in[1];
    const float* Wb     = (const float*)d_in[2];
    const float* conv_w = (const float*)d_in[3];
    const float* conv_b = (const float*)d_in[4];
    const float* theta  = (const float*)d_in[5];
    const float* memory = (const float*)d_in[6];
    const float* a_vec  = (const float*)d_in[7];
    const float* cw     = (const float*)d_in[8];
    const float* cwa    = (const float*)d_in[9];
    const float* fcw    = (const float*)d_in[10];
    const float* fcb    = (const float*)d_in[11];
    const float* emb    = (const float*)d_in[12];
    float* out = (float*)d_out;

    const int smem1 = (CC*130 + CC*TT) * 4;   // 99328 bytes
    cudaFuncSetAttribute(k1_kernel, cudaFuncAttributeMaxDynamicSharedMemorySize, smem1);
    cudaFuncSetAttribute(k4_kernel, cudaFuncAttributeMaxDynamicSharedMemorySize, smem1);

    k0_kernel<<<CC, CC>>>(conv_w, theta);
    k1_kernel<<<BB*NN, 256, smem1>>>(x, Ww, Wb, a_vec);
    k2a_kernel<<<dim3(8,8,16), 256>>>(memory);
    k2b_kernel<<<BB*NN, 256>>>(cw, cwa, fcw, fcb);
    k3_kernel<<<dim3(8,CC,BB), 256>>>();
    k4_kernel<<<BB*NN, 256, smem1>>>(x, conv_b, emb, out);
}

// round 5
// speedup vs baseline: 1.9122x; 1.9122x over previous
#include <cuda_runtime.h>
#include <mma.h>
#include <math.h>
#include <cstdint>

using namespace nvcuda;

#define BB 8
#define CC 128
#define NN 512
#define TT 64
#define SS (NN*TT)
#define KTOP 409

__device__ float g_xw [(size_t)BB*CC*SS];   // [b][c][n][t]
__device__ float g_xh [(size_t)BB*CC*SS];   // [b][c][m][t]
__device__ float g_h  [(size_t)BB*NN*CC];
__device__ float g_wh1[BB*NN];
__device__ float g_wh2[BB*NN];
__device__ float g_s  [(size_t)2*BB*NN*NN];
__device__ float g_adj[(size_t)BB*NN*NN];
__device__ float g_M  [CC*CC];

#define AP 36      // A smem ld (row-major [m][k])
#define BP 132     // B smem ld ([k][n])
#define CP 132     // C smem ld
#define GSMEM 67584

// ---------- K0: M = conv_w @ theta^T ----------
__global__ void k0_kernel(const float* __restrict__ conv_w,
                          const float* __restrict__ theta)
{
    int d = blockIdx.x, e = threadIdx.x;
    float s = 0.f;
    #pragma unroll 8
    for (int c = 0; c < CC; c++)
        s += __ldg(conv_w + d*CC + c) * __ldg(theta + e*CC + c);
    g_M[d*CC + e] = s;
}

// ---------- GEMM1: xw[b][d][s] = Ww·x + bias ; fused h ----------
__global__ void __launch_bounds__(256) kg1(const float* __restrict__ Ww,
                                           const float* __restrict__ Wb,
                                           const float* __restrict__ x)
{
    extern __shared__ float sm[];
    float* As = sm;            // [128][36]
    float* Bs = sm + 4608;     // [32][132]
    float* Cs = sm;            // [128][132]
    const int tid = threadIdx.x, b = blockIdx.z, s0 = blockIdx.x*128;
    const int wid = tid >> 5;
    const int m0w = (wid & 3)*32, n0w = (wid >> 2)*64;

    wmma::fragment<wmma::accumulator,16,16,8,float> acc[2][4];
    #pragma unroll
    for (int i=0;i<2;i++)
        #pragma unroll
        for (int j=0;j<4;j++) wmma::fill_fragment(acc[i][j], 0.f);

    for (int ch = 0; ch < 4; ch++){
        int c0 = ch*32;
        #pragma unroll
        for (int it=0; it<4; it++){
            int slot = tid + it*256, r = slot>>3, q = slot&7;
            float4 v = *(const float4*)(Ww + r*CC + c0 + q*4);
            float* d = As + r*AP + q*4;
            d[0]=wmma::__float_to_tf32(v.x); d[1]=wmma::__float_to_tf32(v.y);
            d[2]=wmma::__float_to_tf32(v.z); d[3]=wmma::__float_to_tf32(v.w);
        }
        #pragma unroll
        for (int it=0; it<4; it++){
            int slot = tid + it*256, r = slot>>5, q = slot&31;
            float4 v = *(const float4*)(x + (size_t)(b*CC + c0 + r)*SS + s0 + q*4);
            float* d = Bs + r*BP + q*4;
            d[0]=wmma::__float_to_tf32(v.x); d[1]=wmma::__float_to_tf32(v.y);
            d[2]=wmma::__float_to_tf32(v.z); d[3]=wmma::__float_to_tf32(v.w);
        }
        __syncthreads();
        #pragma unroll
        for (int k8=0; k8<4; k8++){
            wmma::fragment<wmma::matrix_a,16,16,8,wmma::precision::tf32,wmma::row_major> af[2];
            wmma::fragment<wmma::matrix_b,16,16,8,wmma::precision::tf32,wmma::row_major> bf[4];
            #pragma unroll
            for (int i=0;i<2;i++) wmma::load_matrix_sync(af[i], As + (m0w+i*16)*AP + k8*8, AP);
            #pragma unroll
            for (int j=0;j<4;j++) wmma::load_matrix_sync(bf[j], Bs + k8*8*BP + n0w + j*16, BP);
            #pragma unroll
            for (int i=0;i<2;i++)
                #pragma unroll
                for (int j=0;j<4;j++) wmma::mma_sync(acc[i][j], af[i], bf[j], acc[i][j]);
        }
        __syncthreads();
    }
    #pragma unroll
    for (int i=0;i<2;i++)
        #pragma unroll
        for (int j=0;j<4;j++)
            wmma::store_matrix_sync(Cs + (m0w+i*16)*CP + n0w + j*16, acc[i][j], CP, wmma::mem_row_major);
    __syncthreads();

    float* outp = g_xw + (size_t)(b*CC)*SS + s0;
    #pragma unroll
    for (int it=0; it<16; it++){
        int slot = tid + it*256, d = slot>>5, q = slot&31;
        float bias = Wb[d];
        float4 v = *(float4*)(Cs + d*CP + q*4);
        v.x += bias; v.y += bias; v.z += bias; v.w += bias;
        *(float4*)(outp + (size_t)d*SS + q*4) = v;
    }
    int dd = tid & 127, nl = tid >> 7;
    float hs = 0.f;
    #pragma unroll 16
    for (int t=0; t<64; t++) hs += Cs[dd*CP + nl*64 + t];
    g_h[((size_t)b*NN + (s0>>6) + nl)*CC + dd] = hs + 64.f*Wb[dd];
}

// ---------- GEMM3: xh[b][c][m][t] = sum_n adj[n][m] * xw[c][n][t] ----------
__global__ void __launch_bounds__(256) kg3()
{
    extern __shared__ float sm[];
    float* As2 = sm;           // [32][132] : [k=n][m]
    float* Bs  = sm + 4608;    // [32][132] : [k=n][(c,t)]
    float* Cs  = sm;           // [128][132]
    const int tid = threadIdx.x, b = blockIdx.z;
    const int c0 = blockIdx.x*2, m0 = blockIdx.y*128;
    const int wid = tid >> 5;
    const int m0w = (wid & 3)*32, n0w = (wid >> 2)*64;

    wmma::fragment<wmma::accumulator,16,16,8,float> acc[2][4];
    #pragma unroll
    for (int i=0;i<2;i++)
        #pragma unroll
        for (int j=0;j<4;j++) wmma::fill_fragment(acc[i][j], 0.f);

    for (int ch = 0; ch < 16; ch++){
        int n0 = ch*32;
        #pragma unroll
        for (int it=0; it<4; it++){
            int slot = tid + it*256, r = slot>>5, q = slot&31;
            float4 v = *(const float4*)(g_adj + (size_t)(b*NN + n0 + r)*NN + m0 + q*4);
            float* d = As2 + r*BP + q*4;
            d[0]=wmma::__float_to_tf32(v.x); d[1]=wmma::__float_to_tf32(v.y);
            d[2]=wmma::__float_to_tf32(v.z); d[3]=wmma::__float_to_tf32(v.w);
        }
        #pragma unroll
        for (int it=0; it<4; it++){
            int slot = tid + it*256, r = slot>>5, q = slot&31;
            int col = q*4, cl = col>>6, t = col&63;
            float4 v = *(const float4*)(g_xw + (size_t)(b*CC + c0 + cl)*SS + (n0 + r)*TT + t);
            float* d = Bs + r*BP + col;
            d[0]=wmma::__float_to_tf32(v.x); d[1]=wmma::__float_to_tf32(v.y);
            d[2]=wmma::__float_to_tf32(v.z); d[3]=wmma::__float_to_tf32(v.w);
        }
        __syncthreads();
        #pragma unroll
        for (int k8=0; k8<4; k8++){
            wmma::fragment<wmma::matrix_a,16,16,8,wmma::precision::tf32,wmma::col_major> af[2];
            wmma::fragment<wmma::matrix_b,16,16,8,wmma::precision::tf32,wmma::row_major> bf[4];
            #pragma unroll
            for (int i=0;i<2;i++) wmma::load_matrix_sync(af[i], As2 + k8*8*BP + m0w + i*16, BP);
            #pragma unroll
            for (int j=0;j<4;j++) wmma::load_matrix_sync(bf[j], Bs + k8*8*BP + n0w + j*16, BP);
            #pragma unroll
            for (int i=0;i<2;i++)
                #pragma unroll
                for (int j=0;j<4;j++) wmma::mma_sync(acc[i][j], af[i], bf[j], acc[i][j]);
        }
        __syncthreads();
    }
    #pragma unroll
    for (int i=0;i<2;i++)
        #pragma unroll
        for (int j=0;j<4;j++)
            wmma::store_matrix_sync(Cs + (m0w+i*16)*CP + n0w + j*16, acc[i][j], CP, wmma::mem_row_major);
    __syncthreads();
    #pragma unroll
    for (int it=0; it<16; it++){
        int slot = tid + it*256, r = slot>>5, q = slot&31;
        int col = q*4, cl = col>>6, t = col&63;
        float4 v = *(float4*)(Cs + r*CP + col);
        *(float4*)(g_xh + (size_t)(b*CC + c0 + cl)*SS + (size_t)(m0 + r)*TT + t) = v;
    }
}

// ---------- GEMM4: out[b][d][s] = (M·xh + cb)*emb + x ----------
__global__ void __launch_bounds__(256) kg4(const float* __restrict__ x,
                                           const float* __restrict__ cb_,
                                           const float* __restrict__ emb,
                                           float* __restrict__ outg)
{
    extern __shared__ float sm[];
    float* As = sm;
    float* Bs = sm + 4608;
    float* Cs = sm;
    const int tid = threadIdx.x, b = blockIdx.z, s0 = blockIdx.x*128;
    const int wid = tid >> 5;
    const int m0w = (wid & 3)*32, n0w = (wid >> 2)*64;

    wmma::fragment<wmma::accumulator,16,16,8,float> acc[2][4];
    #pragma unroll
    for (int i=0;i<2;i++)
        #pragma unroll
        for (int j=0;j<4;j++) wmma::fill_fragment(acc[i][j], 0.f);

    for (int ch = 0; ch < 4; ch++){
        int c0 = ch*32;
        #pragma unroll
        for (int it=0; it<4; it++){
            int slot = tid + it*256, r = slot>>3, q = slot&7;
            float4 v = *(const float4*)(g_M + r*CC + c0 + q*4);
            float* d = As + r*AP + q*4;
            d[0]=wmma::__float_to_tf32(v.x); d[1]=wmma::__float_to_tf32(v.y);
            d[2]=wmma::__float_to_tf32(v.z); d[3]=wmma::__float_to_tf32(v.w);
        }
        #pragma unroll
        for (int it=0; it<4; it++){
            int slot = tid + it*256, r = slot>>5, q = slot&31;
            float4 v = *(const float4*)(g_xh + (size_t)(b*CC + c0 + r)*SS + s0 + q*4);
            float* d = Bs + r*BP + q*4;
            d[0]=wmma::__float_to_tf32(v.x); d[1]=wmma::__float_to_tf32(v.y);
            d[2]=wmma::__float_to_tf32(v.z); d[3]=wmma::__float_to_tf32(v.w);
        }
        __syncthreads();
        #pragma unroll
        for (int k8=0; k8<4; k8++){
            wmma::fragment<wmma::matrix_a,16,16,8,wmma::precision::tf32,wmma::row_major> af[2];
            wmma::fragment<wmma::matrix_b,16,16,8,wmma::precision::tf32,wmma::row_major> bf[4];
            #pragma unroll
            for (int i=0;i<2;i++) wmma::load_matrix_sync(af[i], As + (m0w+i*16)*AP + k8*8, AP);
            #pragma unroll
            for (int j=0;j<4;j++) wmma::load_matrix_sync(bf[j], Bs + k8*8*BP + n0w + j*16, BP);
            #pragma unroll
            for (int i=0;i<2;i++)
                #pragma unroll
                for (int j=0;j<4;j++) wmma::mma_sync(acc[i][j], af[i], bf[j], acc[i][j]);
        }
        __syncthreads();
    }
    #pragma unroll
    for (int i=0;i<2;i++)
        #pragma unroll
        for (int j=0;j<4;j++)
            wmma::store_matrix_sync(Cs + (m0w+i*16)*CP + n0w + j*16, acc[i][j], CP, wmma::mem_row_major);
    __syncthreads();

    #pragma unroll
    for (int it=0; it<16; it++){
        int slot = tid + it*256, d = slot>>5, q = slot&31;
        float bias = cb_[d];
        float ev = emb[d*NN + ((s0 + q*4) >> 6)];
        float4 c = *(float4*)(Cs + d*CP + q*4);
        float4 s = *(const float4*)(x + (size_t)(b*CC + d)*SS + s0 + q*4);
        float4 o = make_float4((c.x+bias)*ev + s.x, (c.y+bias)*ev + s.y,
                               (c.z+bias)*ev + s.z, (c.w+bias)*ev + s.w);
        *(float4*)(outg + (size_t)(b*CC + d)*SS + s0 + q*4) = o;
    }
}

// ---------- wh1/wh2 from h ----------
__global__ void __launch_bounds__(128) k_wh(const float* __restrict__ av)
{
    __shared__ float rb1[4], rb2[4];
    int tid = threadIdx.x, row = blockIdx.x;
    float hv = g_h[(size_t)row*CC + tid];
    float p1 = hv*av[tid], p2 = hv*av[CC+tid];
    #pragma unroll
    for (int o = 16; o; o >>= 1){
        p1 += __shfl_xor_sync(0xffffffffu, p1, o);
        p2 += __shfl_xor_sync(0xffffffffu, p2, o);
    }
    if ((tid & 31) == 0){ rb1[tid>>5] = p1; rb2[tid>>5] = p2; }
    __syncthreads();
    if (tid == 0){
        g_wh1[row] = rb1[0]+rb1[1]+rb1[2]+rb1[3];
        g_wh2[row] = rb2[0]+rb2[1]+rb2[2]+rb2[3];
    }
}

// ---------- K2a: S = relu(scale * A B^T) ----------
__global__ void __launch_bounds__(256) k2a_kernel(const float* __restrict__ mem)
{
    __shared__ float As[64][17];
    __shared__ float Bs[64][17];
    const int z = blockIdx.z, b = z>>1, which = z&1;
    const int n0 = blockIdx.x*64, m0 = blockIdx.y*64;
    const float* A  = g_h + (size_t)b*NN*CC;
    const float* Bp = which ? A : mem;
    float* out = g_s + (size_t)which*BB*NN*NN + (size_t)b*NN*NN;
    const int tid = threadIdx.x;
    const int nl0 = (tid>>4)*4, ml0 = (tid&15)*4;
    const int rr = tid>>2, kq = (tid&3)*4;

    float acc[4][4];
    #pragma unroll
    for (int i=0;i<4;i++)
        #pragma unroll
        for (int j=0;j<4;j++) acc[i][j]=0.f;

    for (int k0=0;k0<CC;k0+=16){
        float4 a4 = *(const float4*)(A  + (size_t)(n0+rr)*CC + k0 + kq);
        As[rr][kq  ]=a4.x; As[rr][kq+1]=a4.y; As[rr][kq+2]=a4.z; As[rr][kq+3]=a4.w;
        float4 b4 = *(const float4*)(Bp + (size_t)(m0+rr)*CC + k0 + kq);
        Bs[rr][kq  ]=b4.x; Bs[rr][kq+1]=b4.y; Bs[rr][kq+2]=b4.z; Bs[rr][kq+3]=b4.w;
        __syncthreads();
        #pragma unroll
        for (int k=0;k<16;k++){
            float ar[4], br[4];
            #pragma unroll
            for (int i=0;i<4;i++) ar[i]=As[nl0+i][k];
            #pragma unroll
            for (int j=0;j<4;j++) br[j]=Bs[ml0+j][k];
            #pragma unroll
            for (int i=0;i<4;i++)
                #pragma unroll
                for (int j=0;j<4;j++) acc[i][j] += ar[i]*br[j];
        }
        __syncthreads();
    }
    const float scale = 0.08838834764831845f;
    #pragma unroll
    for (int i=0;i<4;i++){
        float4 v;
        v.x = fmaxf(acc[i][0]*scale, 0.f);
        v.y = fmaxf(acc[i][1]*scale, 0.f);
        v.z = fmaxf(acc[i][2]*scale, 0.f);
        v.w = fmaxf(acc[i][3]*scale, 0.f);
        *(float4*)(out + (size_t)(n0+nl0+i)*NN + m0 + ml0) = v;
    }
}

// ---------- K2b: softmaxes + combine + softmax + top-k ----------
__device__ __forceinline__ float blkMax(float v, float* buf){
    #pragma unroll
    for (int o=16;o;o>>=1) v = fmaxf(v, __shfl_xor_sync(0xffffffffu,v,o));
    if ((threadIdx.x&31)==0) buf[threadIdx.x>>5]=v;
    __syncthreads();
    float r = buf[0];
    #pragma unroll
    for (int i=1;i<8;i++) r = fmaxf(r, buf[i]);
    __syncthreads();
    return r;
}
__device__ __forceinline__ float blkSum(float v, float* buf){
    #pragma unroll
    for (int o=16;o;o>>=1) v += __shfl_xor_sync(0xffffffffu,v,o);
    if ((threadIdx.x&31)==0) buf[threadIdx.x>>5]=v;
    __syncthreads();
    float r = 0.f;
    #pragma unroll
    for (int i=0;i<8;i++) r += buf[i];
    __syncthreads();
    return r;
}

__global__ void __launch_bounds__(256) k2b_kernel(
    const float* __restrict__ cw,  const float* __restrict__ cwa,
    const float* __restrict__ fcw, const float* __restrict__ fcb)
{
    __shared__ float awrow[NN];
    __shared__ float sb[NN];
    __shared__ float rbuf[8];
    __shared__ int   ibuf[8];
    const int tid = threadIdx.x;
    const int b = blockIdx.x >> 9, n = blockIdx.x & (NN-1);
    const size_t rowoff = ((size_t)b*NN + n)*NN;
    const float* s1r = g_s + rowoff;
    const float* s2r = g_s + (size_t)BB*NN*NN + rowoff;

    float v1[2], v2[2];
    v1[0]=s1r[tid]; v1[1]=s1r[tid+256];
    v2[0]=s2r[tid]; v2[1]=s2r[tid+256];

    float m1 = blkMax(fmaxf(v1[0],v1[1]), rbuf);
    float e1a=expf(v1[0]-m1), e1b=expf(v1[1]-m1);
    float z1 = blkSum(e1a+e1b, rbuf);
    float a1[2] = {e1a/z1, e1b/z1};

    float m2 = blkMax(fmaxf(v2[0],v2[1]), rbuf);
    float e2a=expf(v2[0]-m2), e2b=expf(v2[1]-m2);
    float z2 = blkSum(e2a+e2b, rbuf);
    float a2[2] = {e2a/z2, e2b/z2};

    float wh1n = g_wh1[b*NN+n];
    float f0 = fcw[0], f1 = fcw[1], fb = fcb[0];
    float l[2];
    #pragma unroll
    for (int r=0;r<2;r++){
        int m_ = tid + r*256;
        float af = f0*a1[r] + f1*a2[r] + fb;
        l[r] = (wh1n + g_wh2[b*NN+m_]) * cw[(size_t)n*NN+m_]
             + af * cwa[(size_t)n*NN+m_];
    }
    float lm = blkMax(fmaxf(l[0],l[1]), rbuf);
    float ea = expf(l[0]-lm), eb = expf(l[1]-lm);
    float z  = blkSum(ea+eb, rbuf);
    float aw[2] = {ea/z, eb/z};

    awrow[tid]=aw[0]; awrow[tid+256]=aw[1];
    sb[tid]=aw[0];    sb[tid+256]=aw[1];
    __syncthreads();

    for (int ks=2; ks<=NN; ks<<=1){
        for (int j=ks>>1; j>0; j>>=1){
            #pragma unroll
            for (int rep=0; rep<2; rep++){
                int idx = tid + rep*256;
                int ixj = idx ^ j;
                if (ixj > idx){
                    float x0 = sb[idx], x1 = sb[ixj];
                    bool up = ((idx & ks) == 0);
                    bool sw = up ? (x0 > x1) : (x0 < x1);
                    if (sw){ sb[idx]=x1; sb[ixj]=x0; }
                }
            }
            __syncthreads();
        }
    }
    float thr = sb[NN - KTOP];

    int cgt = (aw[0] > thr) + (aw[1] > thr);
    #pragma unroll
    for (int o=16;o;o>>=1) cgt += __shfl_xor_sync(0xffffffffu,cgt,o);
    if ((tid&31)==0) ibuf[tid>>5]=cgt;
    __syncthreads();
    if (tid==0){
        int tot=0;
        #pragma unroll
        for (int i=0;i<8;i++) tot += ibuf[i];
        int need = KTOP - tot;
        for (int m_=0; m_<NN; m_++){
            float v = awrow[m_];
            if (v == thr){ if (need>0) need--; else awrow[m_] = 0.f; }
        }
    }
    __syncthreads();

    float* outr = g_adj + rowoff;
    #pragma unroll
    for (int r=0;r<2;r++){
        int m_ = tid + r*256;
        float v = awrow[m_];
        outr[m_] = (v >= thr) ? v : 0.f;
    }
}

// ---------- launch ----------
extern "C" void kernel_launch(void* const* d_in, const int* in_sizes, int n_in,
                              void* d_out, int out_size)
{
    const float* x      = (const float*)d_in[0];
    const float* Ww     = (const float*)d_in[1];
    const float* Wb     = (const float*)d_in[2];
    const float* conv_w = (const float*)d_in[3];
    const float* conv_b = (const float*)d_in[4];
    const float* theta  = (const float*)d_in[5];
    const float* memory = (const float*)d_in[6];
    const float* a_vec  = (const float*)d_in[7];
    const float* cw     = (const float*)d_in[8];
    const float* cwa    = (const float*)d_in[9];
    const float* fcw    = (const float*)d_in[10];
    const float* fcb    = (const float*)d_in[11];
    const float* emb    = (const float*)d_in[12];
    float* out = (float*)d_out;

    cudaFuncSetAttribute(kg1, cudaFuncAttributeMaxDynamicSharedMemorySize, GSMEM);
    cudaFuncSetAttribute(kg3, cudaFuncAttributeMaxDynamicSharedMemorySize, GSMEM);
    cudaFuncSetAttribute(kg4, cudaFuncAttributeMaxDynamicSharedMemorySize, GSMEM);

    k0_kernel<<<CC, CC>>>(conv_w, theta);
    kg1<<<dim3(SS/128, 1, BB), 256, GSMEM>>>(Ww, Wb, x);
    k_wh<<<BB*NN, 128>>>(a_vec);
    k2a_kernel<<<dim3(8,8,16), 256>>>(memory);
    k2b_kernel<<<BB*NN, 256>>>(cw, cwa, fcw, fcb);
    kg3<<<dim3(TT, NN/128, BB), 256, GSMEM>>>();
    kg4<<<dim3(SS/128, 1, BB), 256, GSMEM>>>(x, conv_b, emb, out);
}

// round 9
// speedup vs baseline: 1.9235x; 1.0059x over previous
#include <cuda_runtime.h>
#include <mma.h>
#include <math.h>
#include <cstdint>

using namespace nvcuda;

#define BB 8
#define CC 128
#define NN 512
#define TT 64
#define SS (NN*TT)
#define KTOP 409

__device__ float g_y  [(size_t)BB*CC*SS];   // y = W2·x + b2   [b][c][n][t]
__device__ float g_h  [(size_t)BB*NN*CC];
__device__ float g_wh1[BB*NN];
__device__ float g_wh2[BB*NN];
__device__ float g_s  [(size_t)2*BB*NN*NN];
__device__ float g_adj[(size_t)BB*NN*NN];
__device__ float g_M  [CC*CC];
__device__ float g_W2 [CC*CC];
__device__ float g_b2 [CC];

#define AP 36
#define BP 132
#define CP 132
#define GSMEM1 70656
#define GSMEM3 67584
#define KHSMEM 82944

__device__ __forceinline__ void cpa16(float* dst, const float* src){
    uint32_t d = (uint32_t)__cvta_generic_to_shared(dst);
    asm volatile("cp.async.ca.shared.global [%0], [%1], 16;" :: "r"(d), "l"(src));
}
#define CP_COMMIT() asm volatile("cp.async.commit_group;")
#define CP_WAIT1()  asm volatile("cp.async.wait_group 1;")
#define CP_WAIT0()  asm volatile("cp.async.wait_group 0;")

// ---------- K0a: M = conv_w @ theta^T ----------
__global__ void k0a_kernel(const float* __restrict__ conv_w,
                           const float* __restrict__ theta)
{
    int d = blockIdx.x, e = threadIdx.x;
    float s = 0.f;
    #pragma unroll 8
    for (int c = 0; c < CC; c++)
        s += __ldg(conv_w + d*CC + c) * __ldg(theta + e*CC + c);
    g_M[d*CC + e] = s;
}

// ---------- K0b: W2 = M @ Ww ; b2 = M @ Wb ----------
__global__ void k0b_kernel(const float* __restrict__ Ww,
                           const float* __restrict__ Wb)
{
    __shared__ float rb[4];
    int d = blockIdx.x, c = threadIdx.x;
    float s = 0.f;
    #pragma unroll 8
    for (int e = 0; e < CC; e++)
        s += g_M[d*CC + e] * __ldg(Ww + e*CC + c);
    g_W2[d*CC + c] = s;
    float v = g_M[d*CC + c] * __ldg(Wb + c);
    #pragma unroll
    for (int o = 16; o; o >>= 1) v += __shfl_xor_sync(0xffffffffu, v, o);
    if ((c & 31) == 0) rb[c >> 5] = v;
    __syncthreads();
    if (c == 0) g_b2[d] = rb[0]+rb[1]+rb[2]+rb[3];
}

// ---------- kh: h = Ww·(sum_t x) + 64·Wb  (exact fp32) ----------
__global__ void __launch_bounds__(256) kh_kernel(const float* __restrict__ x,
                                                 const float* __restrict__ Ww,
                                                 const float* __restrict__ Wb)
{
    extern __shared__ float sm[];
    float* Ws = sm;              // [128][129]
    float* xs = sm + 128*129;    // [32][132]
    int tid = threadIdx.x, b = blockIdx.y, n0 = blockIdx.x*32;
    #pragma unroll
    for (int it = 0; it < 16; it++){
        int slot = tid + it*256, r = slot >> 5, q = slot & 31;
        float4 v = *(const float4*)(Ww + r*CC + q*4);
        float* dp = Ws + r*129 + q*4;
        dp[0]=v.x; dp[1]=v.y; dp[2]=v.z; dp[3]=v.w;
    }
    #pragma unroll
    for (int it = 0; it < 16; it++){
        int slot = tid + it*256, nl = slot >> 7, c = slot & 127;
        const float* p = x + (size_t)(b*CC + c)*SS + (size_t)(n0 + nl)*TT;
        float s = 0.f;
        #pragma unroll
        for (int t4 = 0; t4 < 16; t4++){
            float4 v = *(const float4*)(p + t4*4);
            s += v.x + v.y + v.z + v.w;
        }
        xs[nl*132 + c] = s;
    }
    __syncthreads();
    int d = tid & 127, half = tid >> 7;
    float bias = 64.f * Wb[d];
    for (int nl = half; nl < 32; nl += 2){
        float s = 0.f;
        #pragma unroll 8
        for (int c = 0; c < 128; c++) s += Ws[d*129 + c] * xs[nl*132 + c];
        g_h[((size_t)b*NN + n0 + nl)*CC + d] = s + bias;
    }
}

// ---------- GEMM1: y[b][d][s] = W2·x + b2  (cp.async double-buffered) ----------
__global__ void __launch_bounds__(256) kg1(const float* __restrict__ x)
{
    extern __shared__ float sm[];
    float* Ab[2] = { sm, sm + 4608 };
    float* Bb[2] = { sm + 9216, sm + 13440 };
    float* Cs = sm;
    const int tid = threadIdx.x, b = blockIdx.z, s0 = blockIdx.x*128;
    const int wid = tid >> 5;
    const int m0w = (wid & 3)*32, n0w = (wid >> 2)*64;

    wmma::fragment<wmma::accumulator,16,16,8,float> acc[2][4];
    #pragma unroll
    for (int i=0;i<2;i++)
        #pragma unroll
        for (int j=0;j<4;j++) wmma::fill_fragment(acc[i][j], 0.f);

    // prefetch chunk 0
    {
        int c0 = 0;
        #pragma unroll
        for (int it=0; it<4; it++){
            int slot = tid + it*256, r = slot>>3, q = slot&7;
            cpa16(Ab[0] + r*AP + q*4, g_W2 + r*CC + c0 + q*4);
        }
        #pragma unroll
        for (int it=0; it<4; it++){
            int slot = tid + it*256, r = slot>>5, q = slot&31;
            cpa16(Bb[0] + r*BP + q*4, x + (size_t)(b*CC + c0 + r)*SS + s0 + q*4);
        }
        CP_COMMIT();
    }
    for (int ch = 0; ch < 4; ch++){
        if (ch + 1 < 4){
            int c0 = (ch+1)*32;
            float* An = Ab[(ch+1)&1];
            float* Bn = Bb[(ch+1)&1];
            #pragma unroll
            for (int it=0; it<4; it++){
                int slot = tid + it*256, r = slot>>3, q = slot&7;
                cpa16(An + r*AP + q*4, g_W2 + r*CC + c0 + q*4);
            }
            #pragma unroll
            for (int it=0; it<4; it++){
                int slot = tid + it*256, r = slot>>5, q = slot&31;
                cpa16(Bn + r*BP + q*4, x + (size_t)(b*CC + c0 + r)*SS + s0 + q*4);
            }
            CP_COMMIT();
            CP_WAIT1();
        } else {
            CP_WAIT0();
        }
        __syncthreads();
        float* As = Ab[ch&1];
        float* Bs = Bb[ch&1];
        #pragma unroll
        for (int k8=0; k8<4; k8++){
            wmma::fragment<wmma::matrix_a,16,16,8,wmma::precision::tf32,wmma::row_major> af[2];
            wmma::fragment<wmma::matrix_b,16,16,8,wmma::precision::tf32,wmma::row_major> bf[4];
            #pragma unroll
            for (int i=0;i<2;i++) wmma::load_matrix_sync(af[i], As + (m0w+i*16)*AP + k8*8, AP);
            #pragma unroll
            for (int j=0;j<4;j++) wmma::load_matrix_sync(bf[j], Bs + k8*8*BP + n0w + j*16, BP);
            #pragma unroll
            for (int i=0;i<2;i++)
                #pragma unroll
                for (int j=0;j<4;j++) wmma::mma_sync(acc[i][j], af[i], bf[j], acc[i][j]);
        }
        __syncthreads();
    }
    #pragma unroll
    for (int i=0;i<2;i++)
        #pragma unroll
        for (int j=0;j<4;j++)
            wmma::store_matrix_sync(Cs + (m0w+i*16)*CP + n0w + j*16, acc[i][j], CP, wmma::mem_row_major);
    __syncthreads();

    float* outp = g_y + (size_t)(b*CC)*SS + s0;
    #pragma unroll
    for (int it=0; it<16; it++){
        int slot = tid + it*256, d = slot>>5, q = slot&31;
        float bias = g_b2[d];
        float4 v = *(float4*)(Cs + d*CP + q*4);
        v.x += bias; v.y += bias; v.z += bias; v.w += bias;
        *(float4*)(outp + (size_t)d*SS + q*4) = v;
    }
}

// ---------- GEMM3: out = (y ⊛ adj + cb)·emb + x  (cp.async double-buffered) ----------
__global__ void __launch_bounds__(256) kg3(const float* __restrict__ x,
                                           const float* __restrict__ cb_,
                                           const float* __restrict__ emb,
                                           float* __restrict__ outg)
{
    extern __shared__ float sm[];
    float* Ab[2] = { sm, sm + 4224 };
    float* Bb[2] = { sm + 8448, sm + 12672 };
    float* Cs = sm;
    const int tid = threadIdx.x, b = blockIdx.z;
    const int c0 = blockIdx.x*2, m0 = blockIdx.y*128;
    const int wid = tid >> 5;
    const int m0w = (wid & 3)*32, n0w = (wid >> 2)*64;
    const float* adjb = g_adj + (size_t)b*NN*NN;

    wmma::fragment<wmma::accumulator,16,16,8,float> acc[2][4];
    #pragma unroll
    for (int i=0;i<2;i++)
        #pragma unroll
        for (int j=0;j<4;j++) wmma::fill_fragment(acc[i][j], 0.f);

    {
        #pragma unroll
        for (int it=0; it<4; it++){
            int slot = tid + it*256, r = slot>>5, q = slot&31;
            cpa16(Ab[0] + r*BP + q*4, adjb + (size_t)r*NN + m0 + q*4);
        }
        #pragma unroll
        for (int it=0; it<4; it++){
            int slot = tid + it*256, r = slot>>5, q = slot&31;
            int col = q*4, cl = col>>6, t = col&63;
            cpa16(Bb[0] + r*BP + col, g_y + (size_t)(b*CC + c0 + cl)*SS + (size_t)r*TT + t);
        }
        CP_COMMIT();
    }
    for (int ch = 0; ch < 16; ch++){
        if (ch + 1 < 16){
            int n0 = (ch+1)*32;
            float* An = Ab[(ch+1)&1];
            float* Bn = Bb[(ch+1)&1];
            #pragma unroll
            for (int it=0; it<4; it++){
                int slot = tid + it*256, r = slot>>5, q = slot&31;
                cpa16(An + r*BP + q*4, adjb + (size_t)(n0+r)*NN + m0 + q*4);
            }
            #pragma unroll
            for (int it=0; it<4; it++){
                int slot = tid + it*256, r = slot>>5, q = slot&31;
                int col = q*4, cl = col>>6, t = col&63;
                cpa16(Bn + r*BP + col, g_y + (size_t)(b*CC + c0 + cl)*SS + (size_t)(n0+r)*TT + t);
            }
            CP_COMMIT();
            CP_WAIT1();
        } else {
            CP_WAIT0();
        }
        __syncthreads();
        float* As2 = Ab[ch&1];
        float* Bs  = Bb[ch&1];
        #pragma unroll
        for (int k8=0; k8<4; k8++){
            wmma::fragment<wmma::matrix_a,16,16,8,wmma::precision::tf32,wmma::col_major> af[2];
            wmma::fragment<wmma::matrix_b,16,16,8,wmma::precision::tf32,wmma::row_major> bf[4];
            #pragma unroll
            for (int i=0;i<2;i++) wmma::load_matrix_sync(af[i], As2 + k8*8*BP + m0w + i*16, BP);
            #pragma unroll
            for (int j=0;j<4;j++) wmma::load_matrix_sync(bf[j], Bs + k8*8*BP + n0w + j*16, BP);
            #pragma unroll
            for (int i=0;i<2;i++)
                #pragma unroll
                for (int j=0;j<4;j++) wmma::mma_sync(acc[i][j], af[i], bf[j], acc[i][j]);
        }
        __syncthreads();
    }
    #pragma unroll
    for (int i=0;i<2;i++)
        #pragma unroll
        for (int j=0;j<4;j++)
            wmma::store_matrix_sync(Cs + (m0w+i*16)*CP + n0w + j*16, acc[i][j], CP, wmma::mem_row_major);
    __syncthreads();
    #pragma unroll
    for (int it=0; it<16; it++){
        int slot = tid + it*256, r = slot>>5, q = slot&31;
        int col = q*4, cl = col>>6, t = col&63;
        int c = c0 + cl;
        float bias = cb_[c];
        float ev = emb[c*NN + m0 + r];
        size_t off = (size_t)(b*CC + c)*SS + (size_t)(m0 + r)*TT + t;
        float4 v = *(float4*)(Cs + r*CP + col);
        float4 s = *(const float4*)(x + off);
        *(float4*)(outg + off)
            = make_float4((v.x+bias)*ev + s.x, (v.y+bias)*ev + s.y,
                          (v.z+bias)*ev + s.z, (v.w+bias)*ev + s.w);
    }
}

// ---------- wh1/wh2 from h ----------
__global__ void __launch_bounds__(128) k_wh(const float* __restrict__ av)
{
    __shared__ float rb1[4], rb2[4];
    int tid = threadIdx.x, row = blockIdx.x;
    float hv = g_h[(size_t)row*CC + tid];
    float p1 = hv*av[tid], p2 = hv*av[CC+tid];
    #pragma unroll
    for (int o = 16; o; o >>= 1){
        p1 += __shfl_xor_sync(0xffffffffu, p1, o);
        p2 += __shfl_xor_sync(0xffffffffu, p2, o);
    }
    if ((tid & 31) == 0){ rb1[tid>>5] = p1; rb2[tid>>5] = p2; }
    __syncthreads();
    if (tid == 0){
        g_wh1[row] = rb1[0]+rb1[1]+rb1[2]+rb1[3];
        g_wh2[row] = rb2[0]+rb2[1]+rb2[2]+rb2[3];
    }
}

// ---------- K2a: S = relu(scale * A B^T) ----------
__global__ void __launch_bounds__(256) k2a_kernel(const float* __restrict__ mem)
{
    __shared__ float As[64][17];
    __shared__ float Bs[64][17];
    const int z = blockIdx.z, b = z>>1, which = z&1;
    const int n0 = blockIdx.x*64, m0 = blockIdx.y*64;
    const float* A  = g_h + (size_t)b*NN*CC;
    const float* Bp = which ? A : mem;
    float* out = g_s + (size_t)which*BB*NN*NN + (size_t)b*NN*NN;
    const int tid = threadIdx.x;
    const int nl0 = (tid>>4)*4, ml0 = (tid&15)*4;
    const int rr = tid>>2, kq = (tid&3)*4;

    float acc[4][4];
    #pragma unroll
    for (int i=0;i<4;i++)
        #pragma unroll
        for (int j=0;j<4;j++) acc[i][j]=0.f;

    for (int k0=0;k0<CC;k0+=16){
        float4 a4 = *(const float4*)(A  + (size_t)(n0+rr)*CC + k0 + kq);
        As[rr][kq  ]=a4.x; As[rr][kq+1]=a4.y; As[rr][kq+2]=a4.z; As[rr][kq+3]=a4.w;
        float4 b4 = *(const float4*)(Bp + (size_t)(m0+rr)*CC + k0 + kq);
        Bs[rr][kq  ]=b4.x; Bs[rr][kq+1]=b4.y; Bs[rr][kq+2]=b4.z; Bs[rr][kq+3]=b4.w;
        __syncthreads();
        #pragma unroll
        for (int k=0;k<16;k++){
            float ar[4], br[4];
            #pragma unroll
            for (int i=0;i<4;i++) ar[i]=As[nl0+i][k];
            #pragma unroll
            for (int j=0;j<4;j++) br[j]=Bs[ml0+j][k];
            #pragma unroll
            for (int i=0;i<4;i++)
                #pragma unroll
                for (int j=0;j<4;j++) acc[i][j] += ar[i]*br[j];
        }
        __syncthreads();
    }
    const float scale = 0.08838834764831845f;
    #pragma unroll
    for (int i=0;i<4;i++){
        float4 v;
        v.x = fmaxf(acc[i][0]*scale, 0.f);
        v.y = fmaxf(acc[i][1]*scale, 0.f);
        v.z = fmaxf(acc[i][2]*scale, 0.f);
        v.w = fmaxf(acc[i][3]*scale, 0.f);
        *(float4*)(out + (size_t)(n0+nl0+i)*NN + m0 + ml0) = v;
    }
}

// ---------- K2b: softmaxes + combine + softmax + top-k ----------
__device__ __forceinline__ float blkMax(float v, float* buf){
    #pragma unroll
    for (int o=16;o;o>>=1) v = fmaxf(v, __shfl_xor_sync(0xffffffffu,v,o));
    if ((threadIdx.x&31)==0) buf[threadIdx.x>>5]=v;
    __syncthreads();
    float r = buf[0];
    #pragma unroll
    for (int i=1;i<8;i++) r = fmaxf(r, buf[i]);
    __syncthreads();
    return r;
}
__device__ __forceinline__ float blkSum(float v, float* buf){
    #pragma unroll
    for (int o=16;o;o>>=1) v += __shfl_xor_sync(0xffffffffu,v,o);
    if ((threadIdx.x&31)==0) buf[threadIdx.x>>5]=v;
    __syncthreads();
    float r = 0.f;
    #pragma unroll
    for (int i=0;i<8;i++) r += buf[i];
    __syncthreads();
    return r;
}

__global__ void __launch_bounds__(256) k2b_kernel(
    const float* __restrict__ cw,  const float* __restrict__ cwa,
    const float* __restrict__ fcw, const float* __restrict__ fcb)
{
    __shared__ float awrow[NN];
    __shared__ float sb[NN];
    __shared__ float rbuf[8];
    __shared__ int   ibuf[8];
    const int tid = threadIdx.x;
    const int b = blockIdx.x >> 9, n = blockIdx.x & (NN-1);
    const size_t rowoff = ((size_t)b*NN + n)*NN;
    const float* s1r = g_s + rowoff;
    const float* s2r = g_s + (size_t)BB*NN*NN + rowoff;

    float v1[2], v2[2];
    v1[0]=s1r[tid]; v1[1]=s1r[tid+256];
    v2[0]=s2r[tid]; v2[1]=s2r[tid+256];

    float m1 = blkMax(fmaxf(v1[0],v1[1]), rbuf);
    float e1a=expf(v1[0]-m1), e1b=expf(v1[1]-m1);
    float z1 = blkSum(e1a+e1b, rbuf);
    float a1[2] = {e1a/z1, e1b/z1};

    float m2 = blkMax(fmaxf(v2[0],v2[1]), rbuf);
    float e2a=expf(v2[0]-m2), e2b=expf(v2[1]-m2);
    float z2 = blkSum(e2a+e2b, rbuf);
    float a2[2] = {e2a/z2, e2b/z2};

    float wh1n = g_wh1[b*NN+n];
    float f0 = fcw[0], f1 = fcw[1], fb = fcb[0];
    float l[2];
    #pragma unroll
    for (int r=0;r<2;r++){
        int m_ = tid + r*256;
        float af = f0*a1[r] + f1*a2[r] + fb;
        l[r] = (wh1n + g_wh2[b*NN+m_]) * cw[(size_t)n*NN+m_]
             + af * cwa[(size_t)n*NN+m_];
    }
    float lm = blkMax(fmaxf(l[0],l[1]), rbuf);
    float ea = expf(l[0]-lm), eb = expf(l[1]-lm);
    float z  = blkSum(ea+eb, rbuf);
    float aw[2] = {ea/z, eb/z};

    awrow[tid]=aw[0]; awrow[tid+256]=aw[1];
    sb[tid]=aw[0];    sb[tid+256]=aw[1];
    __syncthreads();

    for (int ks=2; ks<=NN; ks<<=1){
        for (int j=ks>>1; j>0; j>>=1){
            #pragma unroll
            for (int rep=0; rep<2; rep++){
                int idx = tid + rep*256;
                int ixj = idx ^ j;
                if (ixj > idx){
                    float x0 = sb[idx], x1 = sb[ixj];
                    bool up = ((idx & ks) == 0);
                    bool sw = up ? (x0 > x1) : (x0 < x1);
                    if (sw){ sb[idx]=x1; sb[ixj]=x0; }
                }
            }
            __syncthreads();
        }
    }
    float thr = sb[NN - KTOP];

    int cgt = (aw[0] > thr) + (aw[1] > thr);
    #pragma unroll
    for (int o=16;o;o>>=1) cgt += __shfl_xor_sync(0xffffffffu,cgt,o);
    if ((tid&31)==0) ibuf[tid>>5]=cgt;
    __syncthreads();
    if (tid==0){
        int tot=0;
        #pragma unroll
        for (int i=0;i<8;i++) tot += ibuf[i];
        int need = KTOP - tot;
        for (int m_=0; m_<NN; m_++){
            float v = awrow[m_];
            if (v == thr){ if (need>0) need--; else awrow[m_] = 0.f; }
        }
    }
    __syncthreads();

    float* outr = g_adj + rowoff;
    #pragma unroll
    for (int r=0;r<2;r++){
        int m_ = tid + r*256;
        float v = awrow[m_];
        outr[m_] = (v >= thr) ? v : 0.f;
    }
}

// ---------- launch ----------
extern "C" void kernel_launch(void* const* d_in, const int* in_sizes, int n_in,
                              void* d_out, int out_size)
{
    const float* x      = (const float*)d_in[0];
    const float* Ww     = (const float*)d_in[1];
    const float* Wb     = (const float*)d_in[2];
    const float* conv_w = (const float*)d_in[3];
    const float* conv_b = (const float*)d_in[4];
    const float* theta  = (const float*)d_in[5];
    const float* memory = (const float*)d_in[6];
    const float* a_vec  = (const float*)d_in[7];
    const float* cw     = (const float*)d_in[8];
    const float* cwa    = (const float*)d_in[9];
    const float* fcw    = (const float*)d_in[10];
    const float* fcb    = (const float*)d_in[11];
    const float* emb    = (const float*)d_in[12];
    float* out = (float*)d_out;

    cudaFuncSetAttribute(kg1, cudaFuncAttributeMaxDynamicSharedMemorySize, GSMEM1);
    cudaFuncSetAttribute(kg3, cudaFuncAttributeMaxDynamicSharedMemorySize, GSMEM3);
    cudaFuncSetAttribute(kh_kernel, cudaFuncAttributeMaxDynamicSharedMemorySize, KHSMEM);

    k0a_kernel<<<CC, CC>>>(conv_w, theta);
    k0b_kernel<<<CC, CC>>>(Ww, Wb);
    kh_kernel<<<dim3(16, BB), 256, KHSMEM>>>(x, Ww, Wb);
    k_wh<<<BB*NN, 128>>>(a_vec);
    k2a_kernel<<<dim3(8,8,16), 256>>>(memory);
    k2b_kernel<<<BB*NN, 256>>>(cw, cwa, fcw, fcb);
    kg1<<<dim3(SS/128, 1, BB), 256, GSMEM1>>>(x);
    kg3<<<dim3(TT, NN/128, BB), 256, GSMEM3>>>(x, conv_b, emb, out);
}